// round 16
// baseline (speedup 1.0000x reference)
#include <cuda_runtime.h>
#include <cuda_fp16.h>

#define ALPHA 0.2f
#define BN_EPS 1e-5f
#define NBLOCKS 148

// kernel A config
#define A_THREADS 512
#define A_WARPS   16
// kernel B config
#define B_THREADS 768
#define B_WARPS   24

typedef unsigned int u32;
typedef unsigned long long u64;

// ---- global scratch (B up to 65536) ----
#define MAXB 65536
__device__ u32    Hs_g[(size_t)MAXB * 320];   // [b][col 0..63][pair 0..4] fp16x2 (rows 2p,2p+1)
__device__ float2 Sc_g[(size_t)MAXB * 10];    // [b][row j]: (s1, s2)

__device__ __forceinline__ u32 pkh(float a, float b){
    __half2 h = __floats2half2_rn(a, b);
    return *(u32*)&h;
}
__device__ __forceinline__ u64 ffma2(u64 a, u64 b, u64 c){
    u64 d; asm("fma.rn.f32x2 %0, %1, %2, %3;" : "=l"(d) : "l"(a), "l"(b), "l"(c)); return d;
}
__device__ __forceinline__ u64 pk(float lo, float hi){
    u64 r; asm("mov.b64 %0, {%1, %2};" : "=l"(r) : "f"(lo), "f"(hi)); return r;
}
__device__ __forceinline__ float hsum(u64 v){
    float x, y; asm("mov.b64 {%0, %1}, %2;" : "=f"(x), "=f"(y) : "l"(v)); return x + y;
}
__device__ __forceinline__ u32 smem_u32(const void* p){
    u32 r; asm("{ .reg .u64 t; cvta.to.shared.u64 t, %1; cvt.u32.u64 %0, t; }" : "=r"(r) : "l"(p));
    return r;
}
__device__ __forceinline__ void ldsm4(u32& r0, u32& r1, u32& r2, u32& r3, u32 addr){
    asm volatile("ldmatrix.sync.aligned.m8n8.x4.shared.b16 {%0,%1,%2,%3}, [%4];"
                 : "=r"(r0), "=r"(r1), "=r"(r2), "=r"(r3) : "r"(addr));
}
__device__ __forceinline__ void ldsm2(u32& r0, u32& r1, u32 addr){
    asm volatile("ldmatrix.sync.aligned.m8n8.x2.shared.b16 {%0,%1}, [%2];"
                 : "=r"(r0), "=r"(r1) : "r"(addr));
}
__device__ __forceinline__ void mma16(float4& d, u32 a0, u32 a1, u32 a2, u32 a3, u32 b0, u32 b1){
    asm("mma.sync.aligned.m16n8k16.row.col.f32.f16.f16.f32 "
        "{%0,%1,%2,%3}, {%4,%5,%6,%7}, {%8,%9}, {%0,%1,%2,%3};"
        : "+f"(d.x), "+f"(d.y), "+f"(d.z), "+f"(d.w)
        : "r"(a0), "r"(a1), "r"(a2), "r"(a3), "r"(b0), "r"(b1));
}

// ============================================================================
// KERNEL A: H_all = x @ W1 (+ folded score cols) for all B*10 rows.
// smem: BF1 ldmatrix layout [0,4608); per-warp xs 2176 u32 at 4608 + w*2176.
// ============================================================================
#define A_SMEM_SLOTS (4608 + A_WARPS*2176)   // 39424 slots = 157696 B

__global__ void __launch_bounds__(A_THREADS, 1) gat_phase1(
    const float* __restrict__ x,  const float* __restrict__ Wt1,
    const float* __restrict__ a11, const float* __restrict__ a21, int B)
{
    extern __shared__ float sm[];
    const int tid = threadIdx.x;

    // fold: w1a = Wt1^T a11, w2a = Wt1^T a21 (temp in xs region)
    {
        float* wtmp = sm + 4608;
        for (int i = tid; i < 250; i += A_THREADS){
            int v = (i >= 125), k = i - v*125;
            const float* av = v ? a21 : a11;
            float s = 0.f;
            #pragma unroll 8
            for (int n = 0; n < 64; n++) s += av[n] * Wt1[n*125 + k];
            wtmp[v*128 + k] = s;
        }
    }
    __syncthreads();

    // bf1: ldmatrix layout [8 q][9 t][2 h] 8x8 fp16 matrices; t=8 = score cols
    {
        const float* w1a = sm + 4608;
        const float* w2a = sm + 4608 + 128;
        u32* bf1 = (u32*)sm;
        for (int i = tid; i < 4608; i += A_THREADS){
            int j = i & 3, r = (i >> 2) & 7;
            int u = (i >> 5) % 18, q = i / 576;
            int t = u >> 1, h = u & 1;
            int k = 16*q + 8*h + 2*j;
            u32 val;
            if (t < 8){
                int n = 8*t + r;
                float w0 = (k   < 125) ? Wt1[n*125 + k    ] : 0.f;
                float w1 = (k+1 < 125) ? Wt1[n*125 + k + 1] : 0.f;
                val = pkh(w0, w1);
            } else {
                const float* wv = (r == 0) ? w1a : w2a;
                if (r < 2){
                    float w0 = (k   < 125) ? wv[k    ] : 0.f;
                    float w1 = (k+1 < 125) ? wv[k + 1] : 0.f;
                    val = pkh(w0, w1);
                } else val = 0u;
            }
            bf1[i] = val;
        }
    }
    __syncthreads();

    const int wid = tid >> 5, lane = tid & 31;
    const int gid = lane >> 2, tig = lane & 3;
    const int lmat = lane >> 3, lrow = lane & 7;

    u32* xs = (u32*)sm + 4608 + wid*2176;            // x rows stride 68
    const u32 bf1s = smem_u32(sm) + (u32)(lmat*128 + lrow*16);

    const int rows = B * 10;
    const int ntiles = (rows + 31) >> 5;

    for (int tile = blockIdx.x * A_WARPS + wid; tile < ntiles; tile += NBLOCKS * A_WARPS){
        const int base = tile * 32;

        // ---- load 32 rows of x -> fp16 (stride 68, pad >=125 zero) ----
        {
            const int L2 = 2*lane;
            #pragma unroll 4
            for (int r = 0; r < 32; r++){
                int gr = base + r; if (gr >= rows) gr = rows - 1;
                int b = gr / 10, j = gr - b*10;
                int inp = (j >= 5), n = j - inp*5;
                const float* src = x + (size_t)b*1250 + n*250 + inp*125;
                u32* dst = xs + r*68;
                dst[lane] = pkh(src[L2], src[L2+1]);
                float c0 = (L2+64 < 125) ? src[L2+64] : 0.f;
                float c1 = (L2+65 < 125) ? src[L2+65] : 0.f;
                dst[lane+32] = pkh(c0, c1);
            }
        }
        __syncwarp();

        // ---- MMA: 2 m-tiles x 9 N-tiles, K=128, bb shared across m-tiles ----
        float4 d1[2][9];
        #pragma unroll
        for (int m = 0; m < 2; m++)
            #pragma unroll
            for (int t = 0; t < 9; t++) d1[m][t] = make_float4(0.f,0.f,0.f,0.f);
        {
            const u32* x00 = xs + gid*68 + tig;
            const u32* x01 = xs + (gid+8)*68 + tig;
            const u32* x10 = x00 + 16*68;
            const u32* x11 = x01 + 16*68;
            #pragma unroll
            for (int q = 0; q < 8; q++){
                u32 a00 = x00[8*q], a01 = x01[8*q], a02 = x00[8*q+4], a03 = x01[8*q+4];
                u32 a10 = x10[8*q], a11r= x11[8*q], a12r= x10[8*q+4], a13 = x11[8*q+4];
                u32 bq = bf1s + q*2304;
                #pragma unroll
                for (int g = 0; g < 4; g++){
                    u32 r0, r1, r2, r3;
                    ldsm4(r0, r1, r2, r3, bq + g*512);
                    mma16(d1[0][2*g],   a00, a01, a02, a03, r0, r1);
                    mma16(d1[0][2*g+1], a00, a01, a02, a03, r2, r3);
                    mma16(d1[1][2*g],   a10, a11r, a12r, a13, r0, r1);
                    mma16(d1[1][2*g+1], a10, a11r, a12r, a13, r2, r3);
                }
                u32 s0, s1;
                ldsm2(s0, s1, bq + 2048);
                mma16(d1[0][8], a00, a01, a02, a03, s0, s1);
                mma16(d1[1][8], a10, a11r, a12r, a13, s0, s1);
            }
        }
        __syncwarp();   // xs reads done before Hrow overlay

        // ---- spill H rows (fp16, stride 36 u32) + store scores ----
        {
            u32* hrw = xs;   // Hrow overlays xs
            #pragma unroll
            for (int m = 0; m < 2; m++){
                #pragma unroll
                for (int t = 0; t < 8; t++){
                    int c4 = 4*t + tig;
                    hrw[(gid   + 16*m)*36 + c4] = pkh(d1[m][t].x, d1[m][t].y);
                    hrw[(gid+8 + 16*m)*36 + c4] = pkh(d1[m][t].z, d1[m][t].w);
                }
                if (tig == 0){
                    int gr0 = base + gid + 16*m;
                    int gr1 = gr0 + 8;
                    if (gr0 < rows){
                        int b = gr0/10, j = gr0 - b*10;
                        Sc_g[(size_t)b*10 + j] = make_float2(d1[m][8].x, d1[m][8].y);
                    }
                    if (gr1 < rows){
                        int b = gr1/10, j = gr1 - b*10;
                        Sc_g[(size_t)b*10 + j] = make_float2(d1[m][8].z, d1[m][8].w);
                    }
                }
            }
        }
        __syncwarp();

        // ---- transposed pair-copy to Hs_g[b][c][p] ----
        {
            const __half* hr = (const __half*)xs;   // stride 72 halves
            int gp0 = base >> 1;
            #pragma unroll 4
            for (int i = 0; i < 32; i++){
                int idx = i*32 + lane;
                int pl = idx >> 6, c = idx & 63;
                int gp = gp0 + pl;
                if (2*gp < rows){
                    int b = gp / 5, p = gp - b*5;
                    __half2 h2v = __halves2half2(hr[(2*pl)*72 + c], hr[(2*pl+1)*72 + c]);
                    Hs_g[(size_t)b*320 + c*5 + p] = *(u32*)&h2v;
                }
            }
        }
        __syncwarp();   // copy reads done before next tile's x stores
    }
}

// ============================================================================
// KERNEL B: per-graph epilogue (softmax1, apply1-MMA from global Hs, BN1,
// layer-2 MMA, softmax2, apply2, BN2, final linear).
// ============================================================================
// smem (slots): BF2 [0,1280) ldmatrix layout; WL2 [1280,5440); SC1 5440; SH1 5448;
// SC2 5456; SH2 5464; BL [5472,5488); per-warp scratch at 5488 + w*1632:
//   hh0 [0,544) hh1 [544,1088) | red overlay [0,936)
//   SB1 [1088,1128)  SB2 [1128,1168)  attnA [1168,1488)  abuf2 [1488,1616)
#define B_SCR 5488
#define B_WSCR 1632
#define B_SMEM_SLOTS (B_SCR + B_WARPS*B_WSCR)   // 44656 slots = 178624 B

__global__ void __launch_bounds__(B_THREADS, 1) gat_phase2(
    const float* __restrict__ g1,  const float* __restrict__ b1,  const float* __restrict__ m1, const float* __restrict__ v1,
    const float* __restrict__ Wt2, const float* __restrict__ a12, const float* __restrict__ a22,
    const float* __restrict__ g2,  const float* __restrict__ b2,  const float* __restrict__ m2, const float* __restrict__ v2,
    const float* __restrict__ Wl,  const float* __restrict__ bl,
    float* __restrict__ out, int B)
{
    extern __shared__ float sm[];
    const int tid = threadIdx.x;

    // fold layer-2 score vectors
    {
        float* wtmp = sm + B_SCR;
        for (int i = tid; i < 128; i += B_THREADS){
            int v = (i >= 64), k = i & 63;
            const float* av = v ? a22 : a12;
            float s = 0.f;
            #pragma unroll 8
            for (int n = 0; n < 32; n++) s += av[n] * Wt2[n*64 + k];
            wtmp[v*64 + k] = s;
        }
    }
    __syncthreads();
    {
        const float* w1a2 = sm + B_SCR;
        const float* w2a2 = sm + B_SCR + 64;
        u32* bf2 = (u32*)sm;
        for (int i = tid; i < 1280; i += B_THREADS){
            int j = i & 3, r = (i >> 2) & 7;
            int u = (i >> 5) % 10, q = i / 320;
            int t = u >> 1, h = u & 1;
            int k = 16*q + 8*h + 2*j;
            u32 val;
            if (t < 4){
                int n = 8*t + r;
                val = pkh(Wt2[n*64 + k], Wt2[n*64 + k + 1]);
            } else {
                const float* wv = (r == 0) ? w1a2 : w2a2;
                val = (r < 2) ? pkh(wv[k], wv[k+1]) : 0u;
            }
            bf2[i] = val;
        }
        float2* wlp = (float2*)(sm + 1280);
        for (int i = tid; i < 13*5*32; i += B_THREADS){
            int k = i / 160, r = i - k*160;
            int n = r >> 5, l = r & 31;
            wlp[i] = make_float2(Wl[k*320 + n*64 + l], Wl[k*320 + n*64 + 32 + l]);
        }
        if (tid < 5){
            float sc = g1[tid] * rsqrtf(v1[tid] + BN_EPS);
            sm[5440+tid] = sc; sm[5448+tid] = b1[tid] - m1[tid]*sc;
            float s2c = g2[tid] * rsqrtf(v2[tid] + BN_EPS);
            sm[5456+tid] = s2c; sm[5464+tid] = b2[tid] - m2[tid]*s2c;
        }
        if (tid < 13) sm[5472+tid] = bl[tid];
    }
    __syncthreads();

    const int wid = tid >> 5, lane = tid & 31;
    const int gid = lane >> 2, tig = lane & 3;
    const int hi_ok = (gid < 2);
    const int lmat = lane >> 3, lrow = lane & 7;

    float* ws = sm + B_SCR + wid*B_WSCR;
    u32*   wsu = (u32*)ws;
    const u32 bf2s = smem_u32(sm) + (u32)(lmat*128 + lrow*16);

    // zero attn A-buffers once per warp
    for (int i = lane; i < 320; i += 32) wsu[1168 + i] = 0u;
    __syncwarp();

    const int node_lo = gid % 5;
    const int node_hi = (gid + 3) % 5;

    const int total_tasks = (B + 1) >> 1;
    for (int task = blockIdx.x * B_WARPS + wid; task < total_tasks;
         task += NBLOCKS * B_WARPS){

        const int b0i = task * 2;
        const int has_b1 = (b0i + 1 < B);
        const int b1i = has_b1 ? (b0i + 1) : b0i;

        // ---- stage scores from global ----
        if (lane < 20){
            int bb_ = lane / 10, j = lane - 10*bb_;
            int b = bb_ ? b1i : b0i;
            *((float2*)(ws + 1088) + bb_*10 + j) = Sc_g[(size_t)b*10 + j];
        }
        __syncwarp();

        // ---- merged layer 1 softmax -> fp16 attn A-buffers ----
        {
            int bb_ = lane / 10, r = lane - 10*bb_;
            int g = r / 5, j = r - 5*g;
            if (lane < 20){
                const float2* sb = (const float2*)(ws + 1088) + bb_*10;
                __half* ab = (__half*)(wsu + 1168) + bb_*320;   // row stride 20 fp16
                float t2j = sb[g*5 + j].y;
                float ex[5], cs = 0.f;
                #pragma unroll
                for (int i = 0; i < 5; i++){
                    float e = sb[g*5 + i].x + t2j;
                    e = (e > 0.f) ? e : ALPHA*e;
                    ex[i] = __expf(e);
                    cs += ex[i];
                }
                float rc = __fdividef(1.f, cs);
                #pragma unroll
                for (int i = 0; i < 5; i++)
                    ab[(g*5 + i)*20 + (g*5 + j)] = __float2half(ex[i]*rc);
            }
        }
        __syncwarp();

        // ---- per batch: apply1-MMA (B from global Hs) -> BN1 -> layer-2 MMA ----
        #pragma unroll
        for (int bi = 0; bi < 2; bi++){
            const u32* ab32 = wsu + 1168 + bi*160;
            u32 aa0 = ab32[gid*10 + tig];
            u32 aa1 = ab32[(gid+8)*10 + tig];
            u32 aa2 = ab32[gid*10 + tig + 4];
            u32 aa3 = ab32[(gid+8)*10 + tig + 4];

            const u32* hsb = Hs_g + (size_t)(bi ? b1i : b0i) * 320;

            float4 dA[8];
            #pragma unroll
            for (int t = 0; t < 8; t++) dA[t] = make_float4(0.f,0.f,0.f,0.f);
            #pragma unroll
            for (int t = 0; t < 8; t++){
                int c = 8*t + gid;
                u32 b0 = hsb[c*5 + tig];
                u32 b1v = (tig == 0) ? hsb[c*5 + 4] : 0u;
                mma16(dA[t], aa0, aa1, aa2, aa3, b0, b1v);
            }

            float4 d2b[5];
            #pragma unroll
            for (int t = 0; t < 5; t++) d2b[t] = make_float4(0.f,0.f,0.f,0.f);
            {
                float sclo = sm[5440 + node_lo], shlo = sm[5448 + node_lo];
                float schi = sm[5440 + node_hi], shhi = sm[5448 + node_hi];
                #pragma unroll
                for (int q = 0; q < 4; q++){
                    float4 lo = dA[2*q], hi = dA[2*q+1];
                    u32 a00 = pkh(fmaxf(0.f, lo.x*sclo + shlo), fmaxf(0.f, lo.y*sclo + shlo));
                    u32 a01 = pkh(fmaxf(0.f, lo.z*schi + shhi), fmaxf(0.f, lo.w*schi + shhi));
                    u32 a02 = pkh(fmaxf(0.f, hi.x*sclo + shlo), fmaxf(0.f, hi.y*sclo + shlo));
                    u32 a03 = pkh(fmaxf(0.f, hi.z*schi + shhi), fmaxf(0.f, hi.w*schi + shhi));
                    u32 bq = bf2s + q*1280;
                    #pragma unroll
                    for (int g = 0; g < 2; g++){
                        u32 r0, r1, r2, r3;
                        ldsm4(r0, r1, r2, r3, bq + g*512);
                        mma16(d2b[2*g],   a00, a01, a02, a03, r0, r1);
                        mma16(d2b[2*g+1], a00, a01, a02, a03, r2, r3);
                    }
                    u32 s0, s1;
                    ldsm2(s0, s1, bq + 1024);
                    mma16(d2b[4], a00, a01, a02, a03, s0, s1);
                }
            }

            // scores2 -> SB2; spill hh rows (f32, stride 34)
            {
                float2* sb2 = (float2*)(ws + 1128) + bi*10;
                if (tig == 0){
                    sb2[gid] = make_float2(d2b[4].x, d2b[4].y);
                    if (hi_ok) sb2[8 + gid] = make_float2(d2b[4].z, d2b[4].w);
                }
                float* hhb = ws + bi*544;
                #pragma unroll
                for (int t = 0; t < 4; t++){
                    int col = 8*t + 2*tig;
                    *(float2*)(hhb + gid*34 + col) = make_float2(d2b[t].x, d2b[t].y);
                    if (hi_ok)
                        *(float2*)(hhb + (gid+8)*34 + col) = make_float2(d2b[t].z, d2b[t].w);
                }
            }
        }
        __syncwarp();

        // ---- merged layer 2 softmax (cross-batch t2) ----
        {
            int bb_ = lane / 10, r = lane - 10*bb_;
            int g = r / 5, j = r - 5*g;
            if (lane < 20){
                const float2* sb2 = (const float2*)(ws + 1128) + bb_*10;
                float* abuf = ws + 1488 + bb_*64;
                float t2j = sb2[(1-g)*5 + j].y;
                float ex[5], cs = 0.f;
                #pragma unroll
                for (int i = 0; i < 5; i++){
                    float e = sb2[g*5 + i].x + t2j;
                    e = (e > 0.f) ? e : ALPHA*e;
                    ex[i] = __expf(e);
                    cs += ex[i];
                }
                float rc = __fdividef(1.f, cs);
                #pragma unroll
                for (int i = 0; i < 5; i++) abuf[g*32 + i*5 + j] = ex[i]*rc;
            }
        }
        __syncwarp();

        // ---- apply2 + BN2 + ReLU (f32) ----
        float y2[2][2][5];
        #pragma unroll
        for (int bi = 0; bi < 2; bi++){
            const float* hhb = ws + bi*544;
            const float* abuf = ws + 1488 + bi*64;
            float hv[2][5];
            #pragma unroll
            for (int g = 0; g < 2; g++)
                #pragma unroll
                for (int j = 0; j < 5; j++)
                    hv[g][j] = hhb[(g*5 + j)*34 + lane];
            #pragma unroll
            for (int g = 0; g < 2; g++)
                #pragma unroll
                for (int i = 0; i < 5; i++){
                    float o2 = 0.f;
                    #pragma unroll
                    for (int j = 0; j < 5; j++)
                        o2 += abuf[g*32 + i*5 + j] * hv[g][j];
                    y2[bi][g][i] = fmaxf(0.f, o2*sm[5456+i] + sm[5464+i]);
                }
        }
        __syncwarp();   // hh reads done before red overlay

        // ---- final linear: partials to smem, 26-lane row sums ----
        u64 f2a[5], f2b[5];
        #pragma unroll
        for (int n = 0; n < 5; n++){
            f2a[n] = pk(y2[0][0][n], y2[0][1][n]);
            f2b[n] = pk(y2[1][0][n], y2[1][1][n]);
        }
        const u64* wlp = (const u64*)(sm + 1280);
        #pragma unroll
        for (int k = 0; k < 13; k++){
            u64 aa = 0ull, ab = 0ull;
            #pragma unroll
            for (int n = 0; n < 5; n++){
                u64 w = wlp[k*160 + n*32 + lane];
                aa = ffma2(f2a[n], w, aa);
                ab = ffma2(f2b[n], w, ab);
            }
            ws[k*36 + lane]        = hsum(aa);
            ws[(13 + k)*36 + lane] = hsum(ab);
        }
        __syncwarp();
        if (lane < 26){
            const float4* rp = (const float4*)(ws + lane*36);
            float s = 0.f;
            #pragma unroll
            for (int j = 0; j < 8; j++){
                float4 v = rp[j];
                s += (v.x + v.y) + (v.z + v.w);
            }
            int k = (lane < 13) ? lane : lane - 13;
            float res = s + sm[5472 + k];
            if (lane < 13)       out[(size_t)b0i*13 + lane] = res;
            else if (has_b1)     out[(size_t)b1i*13 + k]    = res;
        }
        __syncwarp();   // red reads done before next task's hh writes
    }
}

extern "C" void kernel_launch(void* const* d_in, const int* in_sizes, int n_in,
                              void* d_out, int out_size)
{
    const float* x   = (const float*)d_in[0];
    const float* Wt1 = (const float*)d_in[1];
    const float* a11 = (const float*)d_in[2];
    const float* a21 = (const float*)d_in[3];
    const float* g1  = (const float*)d_in[4];
    const float* b1  = (const float*)d_in[5];
    const float* m1  = (const float*)d_in[6];
    const float* v1  = (const float*)d_in[7];
    const float* Wt2 = (const float*)d_in[8];
    const float* a12 = (const float*)d_in[9];
    const float* a22 = (const float*)d_in[10];
    const float* g2  = (const float*)d_in[11];
    const float* b2  = (const float*)d_in[12];
    const float* m2  = (const float*)d_in[13];
    const float* v2  = (const float*)d_in[14];
    const float* Wl  = (const float*)d_in[15];
    const float* bl  = (const float*)d_in[16];

    int B = in_sizes[0] / 1250;
    if (B > MAXB) B = MAXB;

    size_t smemA = (size_t)A_SMEM_SLOTS * 4;
    size_t smemB = (size_t)B_SMEM_SLOTS * 4;
    cudaFuncSetAttribute(gat_phase1, cudaFuncAttributeMaxDynamicSharedMemorySize, (int)smemA);
    cudaFuncSetAttribute(gat_phase2, cudaFuncAttributeMaxDynamicSharedMemorySize, (int)smemB);

    gat_phase1<<<NBLOCKS, A_THREADS, smemA>>>(x, Wt1, a11, a21, B);
    gat_phase2<<<NBLOCKS, B_THREADS, smemB>>>(g1, b1, m1, v1,
                                              Wt2, a12, a22, g2, b2, m2, v2,
                                              Wl, bl, (float*)d_out, B);
}